// round 14
// baseline (speedup 1.0000x reference)
#include <cuda_runtime.h>
#include <cuda_fp16.h>
#include <cstdint>

#define IN_F      256
#define OUT_F     256
#define OUTSTRIDE 512
#define MAXE      3200000
#define MAXM      100000
#define NB        100352          // >= N_NODES, multiple of 256
#define HALF      50176           // dst-partition boundary (NB/2)
#define SLOT_CAP  64              // Poisson(32) tail beyond 64 ~ 4e-7
#define SPILL_MAX 65536

// ---------------- device scratch (allocation-free rule) ---------------------
__device__ __half        g_Wh[OUT_F * IN_F];    // fp16, transposed: [n][k]
__device__ __half        g_ftH[(size_t)MAXM * OUT_F];  // fp16 mirror of ft_input
__device__ int2          g_slots[(size_t)NB * SLOT_CAP]; // {src, val_bits} per dst
__device__ int           g_cnt[NB];
__device__ int4          g_spill[SPILL_MAX];    // {src, dst, val_bits, 0}
__device__ int           g_spill_cnt;
__device__ unsigned      g_idx_is64;

// ---------------- helpers ---------------------------------------------------
static __device__ __forceinline__ uint32_t smem_u32(const void* p) {
    uint32_t a;
    asm("{ .reg .u64 t; cvta.to.shared.u64 t, %1; cvt.u32.u64 %0, t; }"
        : "=r"(a) : "l"(p));
    return a;
}
static __device__ __forceinline__ void ldsm4(uint32_t* r, uint32_t addr) {
    asm volatile("ldmatrix.sync.aligned.m8n8.x4.shared.b16 {%0,%1,%2,%3}, [%4];"
                 : "=r"(r[0]), "=r"(r[1]), "=r"(r[2]), "=r"(r[3]) : "r"(addr));
}
static __device__ __forceinline__ void mma16816f(float* c, const uint32_t* a,
                                                 const uint32_t* b) {
    asm volatile(
        "mma.sync.aligned.m16n8k16.row.col.f32.f16.f16.f32 "
        "{%0,%1,%2,%3}, {%4,%5,%6,%7}, {%8,%9}, {%0,%1,%2,%3};"
        : "+f"(c[0]), "+f"(c[1]), "+f"(c[2]), "+f"(c[3])
        : "r"(a[0]), "r"(a[1]), "r"(a[2]), "r"(a[3]), "r"(b[0]), "r"(b[1]));
}

// ---------------------------------------------------------------------------
// Zero counters + detect index width (int64 vs int32), fused.
// ---------------------------------------------------------------------------
__global__ void zero_detect_kernel(const unsigned* __restrict__ p) {
    int i = blockIdx.x * 256 + threadIdx.x;
    g_cnt[i] = 0;
    if (i == 0) g_spill_cnt = 0;
    if (blockIdx.x == 0) {
        unsigned v = p[2 * threadIdx.x + 1];
        int any = __syncthreads_or(v != 0u);
        if (threadIdx.x == 0) g_idx_is64 = any ? 0u : 1u;
    }
}

// W[k][n] -> transposed fp16: g_Wh[n][k].
__global__ void conv_w_kernel(const float* __restrict__ W) {
    int i = blockIdx.x * blockDim.x + threadIdx.x;   // 65536
    int k = i >> 8, n = i & 255;
    g_Wh[n * IN_F + k] = __float2half_rn(W[i]);
}

// ---------------------------------------------------------------------------
// Direct bucketing for one dst partition [dstLo, dstHi). Reads all edges,
// fills only its partition's buckets; rare overflow -> global spill list.
// ---------------------------------------------------------------------------
__global__ void bucket_kernel(const void* __restrict__ esrc,
                              const void* __restrict__ edst,
                              const float* __restrict__ ev, int E,
                              int dstLo, int dstHi) {
    int i = blockIdx.x * blockDim.x + threadIdx.x;
    if (i >= E) return;
    int d;
    if (g_idx_is64) d = (int)__ldg((const long long*)edst + i);
    else            d = __ldg((const int*)edst + i);
    if (d < dstLo || d >= dstHi) return;
    int s;
    if (g_idx_is64) s = (int)__ldg((const long long*)esrc + i);
    else            s = __ldg((const int*)esrc + i);
    int vb = __float_as_int(__ldg(ev + i));
    int pos = atomicAdd(&g_cnt[d], 1);
    if (pos < SLOT_CAP) {
        g_slots[(size_t)d * SLOT_CAP + pos] = make_int2(s, vb);
    } else {
        int sp = atomicAdd(&g_spill_cnt, 1);
        if (sp < SPILL_MAX) g_spill[sp] = make_int4(s, d, vb, 0);
    }
}

// ---------------------------------------------------------------------------
// GEMM via mma.sync (HMMA.16816 fp16, fp32 accum), single product.
// Block 128x128, 8 warps (warp tile 32x64), K-chunk 32, K=256.
// bnBase selects the N-half. Epilogue writes fp32 out AND fp16 mirror g_ftH.
// ---------------------------------------------------------------------------
#define SSTR 40

__global__ __launch_bounds__(256)
void gemm_mma_kernel(const float* __restrict__ X, float* __restrict__ out,
                     int M, int bnBase) {
    __shared__ __align__(16) __half sA[128 * SSTR];
    __shared__ __align__(16) __half sB[128 * SSTR];

    const int tid  = threadIdx.x;
    const int lane = tid & 31, wid = tid >> 5;
    const int bm = blockIdx.x * 128;
    const int bn = bnBase;
    const int wm = (wid & 3) * 32;
    const int wn = (wid >> 2) * 64;

    float acc[2][8][4];
#pragma unroll
    for (int i = 0; i < 2; i++)
#pragma unroll
        for (int j = 0; j < 8; j++)
#pragma unroll
            for (int k = 0; k < 4; k++) acc[i][j][k] = 0.f;

    const int rA = ((lane >> 3) & 1) * 8 + (lane & 7);
    const int kA = (lane >> 4) * 8;
    const int rB = (lane >> 4) * 8 + (lane & 7);
    const int kB = ((lane >> 3) & 1) * 8;

    const uint32_t aB = smem_u32(sA), bB = smem_u32(sB);

    for (int kc = 0; kc < 8; kc++) {
        const int k0 = kc * 32;
        __syncthreads();
        // A fill: fp32 -> fp16
#pragma unroll
        for (int i = 0; i < 4; i++) {
            int idx = tid + i * 256;
            int row = idx >> 3, c = idx & 7;
            float4 v = make_float4(0.f, 0.f, 0.f, 0.f);
            if (bm + row < M)
                v = __ldg(reinterpret_cast<const float4*>(
                        X + (size_t)(bm + row) * IN_F + k0 + c * 4));
            __half2 h01 = __floats2half2_rn(v.x, v.y);
            __half2 h23 = __floats2half2_rn(v.z, v.w);
            uint2 ph;
            ph.x = *reinterpret_cast<uint32_t*>(&h01);
            ph.y = *reinterpret_cast<uint32_t*>(&h23);
            *reinterpret_cast<uint2*>(&sA[row * SSTR + c * 4]) = ph;
        }
        // B fill: fp16 straight copy
#pragma unroll
        for (int i = 0; i < 4; i++) {
            int idx = tid + i * 256;
            int row = idx >> 3, c = idx & 7;
            *reinterpret_cast<uint2*>(&sB[row * SSTR + c * 4]) =
                __ldg(reinterpret_cast<const uint2*>(
                    g_Wh + (size_t)(bn + row) * IN_F + k0 + c * 4));
        }
        __syncthreads();

#pragma unroll
        for (int ks = 0; ks < 2; ks++) {
            uint32_t a[2][4], b[4][4];
            const uint32_t kOffA = (uint32_t)((ks * 16 + kA) * 2);
            const uint32_t kOffB = (uint32_t)((ks * 16 + kB) * 2);
#pragma unroll
            for (int am = 0; am < 2; am++)
                ldsm4(a[am], aB + (wm + am * 16 + rA) * (SSTR * 2) + kOffA);
#pragma unroll
            for (int nb = 0; nb < 4; nb++)
                ldsm4(b[nb], bB + (wn + nb * 16 + rB) * (SSTR * 2) + kOffB);
#pragma unroll
            for (int am = 0; am < 2; am++)
#pragma unroll
                for (int j = 0; j < 8; j++)
                    mma16816f(acc[am][j], a[am], &b[j >> 1][(j & 1) * 2]);
        }
    }

    const int crow = lane >> 2, ccol = (lane & 3) * 2;
#pragma unroll
    for (int am = 0; am < 2; am++) {
#pragma unroll
        for (int j = 0; j < 8; j++) {
            int col = bn + wn + j * 8 + ccol;
            int r0  = bm + wm + am * 16 + crow;
            if (r0 < M) {
                *reinterpret_cast<float2*>(out + (size_t)r0 * OUTSTRIDE + col) =
                    make_float2(acc[am][j][0], acc[am][j][1]);
                *reinterpret_cast<__half2*>(g_ftH + (size_t)r0 * OUT_F + col) =
                    __floats2half2_rn(acc[am][j][0], acc[am][j][1]);
            }
            int r1 = r0 + 8;
            if (r1 < M) {
                *reinterpret_cast<float2*>(out + (size_t)r1 * OUTSTRIDE + col) =
                    make_float2(acc[am][j][2], acc[am][j][3]);
                *reinterpret_cast<__half2*>(g_ftH + (size_t)r1 * OUT_F + col) =
                    __floats2half2_rn(acc[am][j][2], acc[am][j][3]);
            }
        }
    }
}

// ---------------------------------------------------------------------------
// Full-width scatter over dst range [dstBase, dstEnd): one warp per dst node,
// 256 features (lane -> 8). fp16 gathers, fp32 accumulate, 2 STG.128/lane.
// Unconditional store also zeroes empty dst nodes.
// ---------------------------------------------------------------------------
__global__ __launch_bounds__(256)
void scatter_full_kernel(float* out, int dstBase, int dstEnd) {
    const int d    = dstBase + ((blockIdx.x * blockDim.x + threadIdx.x) >> 5);
    const int lane = threadIdx.x & 31;
    if (d >= dstEnd) return;

    const int cnt = min(__ldg(&g_cnt[d]), SLOT_CAP);
    const int2* slots = g_slots + (size_t)d * SLOT_CAP;

    float4 a0 = make_float4(0.f, 0.f, 0.f, 0.f);
    float4 a1 = make_float4(0.f, 0.f, 0.f, 0.f);

    for (int base = 0; base < cnt; base += 32) {
        const int n = min(32, cnt - base);
        int2 rec;
        if (lane < n) rec = __ldg(&slots[base + lane]);
        for (int j = 0; j < n; j++) {
            int   s = __shfl_sync(0xffffffffu, rec.x, j);
            float v = __int_as_float(__shfl_sync(0xffffffffu, rec.y, j));
            uint4 raw = __ldg(reinterpret_cast<const uint4*>(
                                  g_ftH + (size_t)s * OUT_F) + lane);
            float2 f0 = __half22float2(*reinterpret_cast<__half2*>(&raw.x));
            float2 f1 = __half22float2(*reinterpret_cast<__half2*>(&raw.y));
            float2 f2 = __half22float2(*reinterpret_cast<__half2*>(&raw.z));
            float2 f3 = __half22float2(*reinterpret_cast<__half2*>(&raw.w));
            a0.x += v * f0.x;  a0.y += v * f0.y;
            a0.z += v * f1.x;  a0.w += v * f1.y;
            a1.x += v * f2.x;  a1.y += v * f2.y;
            a1.z += v * f3.x;  a1.w += v * f3.y;
        }
    }
    float* dst = out + (size_t)d * OUTSTRIDE + OUT_F + lane * 8;
    *reinterpret_cast<float4*>(dst)     = a0;
    *reinterpret_cast<float4*>(dst + 4) = a1;
}

// ---------------------------------------------------------------------------
// Spill cleanup: atomically add the (rare) overflow edges into the output.
// ---------------------------------------------------------------------------
__global__ void spill_kernel(float* out) {
    const int total  = min(g_spill_cnt, SPILL_MAX);
    const int lane   = threadIdx.x & 31;
    const int warpId = (blockIdx.x * blockDim.x + threadIdx.x) >> 5;
    const int nW     = (gridDim.x * blockDim.x) >> 5;

    for (int i = warpId; i < total; i += nW) {
        int4 r = g_spill[i];
        float v = __int_as_float(r.z);
        uint4 raw = __ldg(reinterpret_cast<const uint4*>(
                              g_ftH + (size_t)r.x * OUT_F) + lane);
        float2 f0 = __half22float2(*reinterpret_cast<__half2*>(&raw.x));
        float2 f1 = __half22float2(*reinterpret_cast<__half2*>(&raw.y));
        float2 f2 = __half22float2(*reinterpret_cast<__half2*>(&raw.z));
        float2 f3 = __half22float2(*reinterpret_cast<__half2*>(&raw.w));
        float* dp = out + (size_t)r.y * OUTSTRIDE + OUT_F + lane * 8;
        asm volatile("red.global.add.v4.f32 [%0], {%1,%2,%3,%4};"
                     :: "l"(dp), "f"(v * f0.x), "f"(v * f0.y),
                        "f"(v * f1.x), "f"(v * f1.y) : "memory");
        asm volatile("red.global.add.v4.f32 [%0], {%1,%2,%3,%4};"
                     :: "l"(dp + 4), "f"(v * f2.x), "f"(v * f2.y),
                        "f"(v * f3.x), "f"(v * f3.y) : "memory");
    }
}

// ---------------------------------------------------------------------------
extern "C" void kernel_launch(void* const* d_in, const int* in_sizes, int n_in,
                              void* d_out, int out_size) {
    const float* input  = (const float*)d_in[0];   // [N, 256]
    const void*  esrc   = d_in[1];
    const void*  edst   = d_in[2];
    const float* evals  = (const float*)d_in[3];
    const float* weight = (const float*)d_in[4];   // [256, 256]
    float* out = (float*)d_out;                    // [N, 512]

    const int M = in_sizes[0] / IN_F;              // 100000
    const int E = in_sizes[1];                     // 3200000

    static cudaStream_t s1 = nullptr, s2 = nullptr;
    static cudaEvent_t evRoot, evA, evB, evC, ev2;
    if (!s1) {   // one-time resource creation (not memory allocation)
        cudaStreamCreateWithFlags(&s1, cudaStreamNonBlocking);
        cudaStreamCreateWithFlags(&s2, cudaStreamNonBlocking);
        cudaEventCreateWithFlags(&evRoot, cudaEventDisableTiming);
        cudaEventCreateWithFlags(&evA,    cudaEventDisableTiming);
        cudaEventCreateWithFlags(&evB,    cudaEventDisableTiming);
        cudaEventCreateWithFlags(&evC,    cudaEventDisableTiming);
        cudaEventCreateWithFlags(&ev2,    cudaEventDisableTiming);
    }

    const int dstHiA = (M < HALF) ? M : HALF;

    // ---- fork side stream s1 for the bucketing chain ----
    cudaEventRecord(evRoot, 0);
    cudaStreamWaitEvent(s1, evRoot, 0);

    // s1: zero+detect, then bucket partition A (dst < HALF), then partition B
    zero_detect_kernel<<<NB / 256, 256, 0, s1>>>((const unsigned*)esrc);
    bucket_kernel<<<(E + 255) / 256, 256, 0, s1>>>(esrc, edst, evals, E,
                                                   0, dstHiA);
    cudaEventRecord(evA, s1);
    if (M > dstHiA)
        bucket_kernel<<<(E + 255) / 256, 256, 0, s1>>>(esrc, edst, evals, E,
                                                       dstHiA, M);
    cudaEventRecord(evB, s1);

    // s0: convert W -> evC
    conv_w_kernel<<<(IN_F * OUT_F) / 256, 256>>>(weight);
    cudaEventRecord(evC, 0);

    // s2: GEMM half 1 (cols 128-255) right after conv_w
    cudaStreamWaitEvent(s2, evC, 0);
    dim3 gg((M + 127) / 128, 1);
    gemm_mma_kernel<<<gg, 256, 0, s2>>>(input, out, M, 128);
    cudaEventRecord(ev2, s2);

    // s0: GEMM half 0 (cols 0-127)
    gemm_mma_kernel<<<gg, 256>>>(input, out, M, 0);

    // s0: scatter partition A (needs bucketA + both GEMM halves);
    //     bucketB fills concurrently on s1.
    cudaStreamWaitEvent(0, evA, 0);
    cudaStreamWaitEvent(0, ev2, 0);
    scatter_full_kernel<<<(dstHiA * 32 + 255) / 256, 256>>>(out, 0, dstHiA);

    // s0: scatter partition B, then spill cleanup
    cudaStreamWaitEvent(0, evB, 0);
    if (M > dstHiA)
        scatter_full_kernel<<<((M - dstHiA) * 32 + 255) / 256, 256>>>(
            out, dstHiA, M);
    spill_kernel<<<32, 256>>>(out);
}